// round 4
// baseline (speedup 1.0000x reference)
#include <cuda_runtime.h>
#include <cuda_fp16.h>
#include <math.h>

#define NN_NODES 100000
#define EE_EDGES 3200000
#define FDIM 256
#define CDIM 64
#define LN_EPS 1e-5

// ---------------- scratch (static device globals; no allocation) ----------------
__device__ int    g_deg_s[NN_NODES];
__device__ int    g_deg_d[NN_NODES];
__device__ float  g_norm_s[NN_NODES];
__device__ float  g_norm_d[NN_NODES];
__device__ int    g_row_off[NN_NODES + 1];
__device__ int    g_cursor[NN_NODES];
__device__ int    g_col[EE_EDGES];
__device__ __half g_x16[(size_t)NN_NODES * FDIM];   // fp16 input features
__device__ __half g_h16[(size_t)NN_NODES * FDIM];   // fp16 hidden
__device__ float  g_agg[(size_t)NN_NODES * FDIM];   // fp32 aggregate (GEMM A)
__device__ float  g_t[(size_t)NN_NODES * CDIM];     // fp32 layer-3 GEMM out
__device__ double g_stats[2];   // sum, sumsq
__device__ float  g_ln[2];      // mu, inv_std

// ---------------- setup kernels ----------------
__global__ void k_init() {
    int i = blockIdx.x * blockDim.x + threadIdx.x;
    if (i < NN_NODES) { g_deg_s[i] = 0; g_deg_d[i] = 0; }
    if (i == 0) { g_stats[0] = 0.0; g_stats[1] = 0.0; }
}

__global__ void k_degrees(const int* __restrict__ src, const int* __restrict__ dst) {
    int e = blockIdx.x * blockDim.x + threadIdx.x;
    if (e < EE_EDGES) {
        atomicAdd(&g_deg_s[src[e]], 1);
        atomicAdd(&g_deg_d[dst[e]], 1);
    }
}

__global__ void k_scan() {
    const int T = 1024;
    int t = threadIdx.x;
    const int chunk = (NN_NODES + T - 1) / T;
    int beg = t * chunk;
    int end = min(beg + chunk, NN_NODES);
    int local = 0;
    for (int i = beg; i < end; i++) local += g_deg_d[i];

    __shared__ int sh[T];
    sh[t] = local;
    __syncthreads();
    for (int off = 1; off < T; off <<= 1) {
        int v = (t >= off) ? sh[t - off] : 0;
        __syncthreads();
        sh[t] += v;
        __syncthreads();
    }
    int run = sh[t] - local;
    for (int i = beg; i < end; i++) {
        g_row_off[i] = run;
        g_cursor[i] = run;
        run += g_deg_d[i];
    }
    if (t == T - 1) g_row_off[NN_NODES] = sh[T - 1];

    for (int i = beg; i < end; i++) {
        g_norm_s[i] = rsqrtf((float)max(g_deg_s[i], 1));
        g_norm_d[i] = rsqrtf((float)max(g_deg_d[i], 1));
    }
}

__global__ void k_fill(const int* __restrict__ src, const int* __restrict__ dst) {
    int e = blockIdx.x * blockDim.x + threadIdx.x;
    if (e < EE_EDGES) {
        int p = atomicAdd(&g_cursor[dst[e]], 1);
        g_col[p] = src[e];
    }
}

// fp32 -> fp16 convert (8 elements/thread)
__global__ void k_cvt(const float* __restrict__ x, __half* __restrict__ y, int n8) {
    int i = blockIdx.x * blockDim.x + threadIdx.x;
    if (i >= n8) return;
    float4 a = reinterpret_cast<const float4*>(x)[i * 2];
    float4 b = reinterpret_cast<const float4*>(x)[i * 2 + 1];
    __half2 h[4];
    h[0] = __floats2half2_rn(a.x, a.y);
    h[1] = __floats2half2_rn(a.z, a.w);
    h[2] = __floats2half2_rn(b.x, b.y);
    h[3] = __floats2half2_rn(b.z, b.w);
    reinterpret_cast<float4*>(y)[i] = *reinterpret_cast<float4*>(h);
}

// ---------------- SpMM: pull (warp per dst row), fp16 features, fp32 accum ----------------
template <bool LN>
__global__ void k_spmm256(const __half* __restrict__ hin, float* __restrict__ out) {
    int gw = (blockIdx.x * blockDim.x + threadIdx.x) >> 5;
    int lane = threadIdx.x & 31;
    if (gw >= NN_NODES) return;

    float mu = 0.f, inv = 1.f;
    if (LN) { mu = g_ln[0]; inv = g_ln[1]; }

    int s0 = g_row_off[gw], s1 = g_row_off[gw + 1];
    float acc[8];
#pragma unroll
    for (int t = 0; t < 8; t++) acc[t] = 0.f;

    const float4* __restrict__ h4 = reinterpret_cast<const float4*>(hin); // 8 halves each

    for (int base = s0; base < s1; base += 32) {
        int kk = base + lane;
        int j = 0; float sc = 0.f;
        if (kk < s1) { j = g_col[kk]; sc = g_norm_s[j]; }
        int cnt = min(32, s1 - base);
#pragma unroll 8
        for (int i = 0; i < cnt; i++) {
            int   jj = __shfl_sync(0xffffffffu, j, i);
            float sj = __shfl_sync(0xffffffffu, sc, i);
            float4 raw = h4[(size_t)jj * 32 + lane];    // 8 halves
            const __half2* hp = reinterpret_cast<const __half2*>(&raw);
            float2 f0 = __half22float2(hp[0]);
            float2 f1 = __half22float2(hp[1]);
            float2 f2 = __half22float2(hp[2]);
            float2 f3 = __half22float2(hp[3]);
            float sv = LN ? (sj * inv) : sj;
            if (LN) {
                acc[0] = fmaf(f0.x - mu, sv, acc[0]); acc[1] = fmaf(f0.y - mu, sv, acc[1]);
                acc[2] = fmaf(f1.x - mu, sv, acc[2]); acc[3] = fmaf(f1.y - mu, sv, acc[3]);
                acc[4] = fmaf(f2.x - mu, sv, acc[4]); acc[5] = fmaf(f2.y - mu, sv, acc[5]);
                acc[6] = fmaf(f3.x - mu, sv, acc[6]); acc[7] = fmaf(f3.y - mu, sv, acc[7]);
            } else {
                acc[0] = fmaf(f0.x, sv, acc[0]); acc[1] = fmaf(f0.y, sv, acc[1]);
                acc[2] = fmaf(f1.x, sv, acc[2]); acc[3] = fmaf(f1.y, sv, acc[3]);
                acc[4] = fmaf(f2.x, sv, acc[4]); acc[5] = fmaf(f2.y, sv, acc[5]);
                acc[6] = fmaf(f3.x, sv, acc[6]); acc[7] = fmaf(f3.y, sv, acc[7]);
            }
        }
    }
    float nd = g_norm_d[gw];
    float4 o0 = make_float4(acc[0] * nd, acc[1] * nd, acc[2] * nd, acc[3] * nd);
    float4 o1 = make_float4(acc[4] * nd, acc[5] * nd, acc[6] * nd, acc[7] * nd);
    float4* o4 = reinterpret_cast<float4*>(out);
    o4[(size_t)gw * 64 + lane * 2]     = o0;
    o4[(size_t)gw * 64 + lane * 2 + 1] = o1;
}

// ---------------- SpMM 64-wide (final layer, with bias) ----------------
__global__ void k_spmm64(const float* __restrict__ tin, const float* __restrict__ bias,
                         float* __restrict__ out) {
    int gw = (blockIdx.x * blockDim.x + threadIdx.x) >> 5;
    int lane = threadIdx.x & 31;
    if (gw >= NN_NODES) return;

    int s0 = g_row_off[gw], s1 = g_row_off[gw + 1];
    float2 a = make_float2(0.f, 0.f);
    const float2* __restrict__ t2 = reinterpret_cast<const float2*>(tin);

    for (int base = s0; base < s1; base += 32) {
        int kk = base + lane;
        int j = 0; float sc = 0.f;
        if (kk < s1) { j = g_col[kk]; sc = g_norm_s[j]; }
        int cnt = min(32, s1 - base);
#pragma unroll 8
        for (int i = 0; i < cnt; i++) {
            int   jj = __shfl_sync(0xffffffffu, j, i);
            float sj = __shfl_sync(0xffffffffu, sc, i);
            float2 v = t2[(size_t)jj * (CDIM / 2) + lane];
            a.x = fmaf(v.x, sj, a.x);
            a.y = fmaf(v.y, sj, a.y);
        }
    }
    float nd = g_norm_d[gw];
    float2 b = reinterpret_cast<const float2*>(bias)[lane];
    float2 o;
    o.x = fmaf(a.x, nd, b.x);
    o.y = fmaf(a.y, nd, b.y);
    reinterpret_cast<float2*>(out)[(size_t)gw * (CDIM / 2) + lane] = o;
}

// ---------------- fp16 tensor-core GEMM, B split hi+lo (B exact) ----------------
// C[M,Nn] = op(A[M,K]) @ B[K,Nn]; A rounded to fp16 once; B = Bh + Bl (fp16 pair).
// mma.sync.m16n8k16.f16.f16.f32, 2 MMAs per frag-pair per k-step.
template <int BM, int BN, int WM, int WN, bool BIAS_RELU, bool STATS, bool LNA,
          bool A_HALF, bool C_HALF>
__global__ void k_gemm16(const void* __restrict__ Ap, const float* __restrict__ B,
                         const float* __restrict__ bias, void* __restrict__ Cp,
                         int M, int Nn, int K) {
    constexpr int BK = 32;
    constexpr int LDA = BK + 8;          // halves; 80B row pitch -> conflict-free frags
    constexpr int LDB = BK + 8;          // B transposed [n][k] halves
    constexpr int NWARP = (BM / WM) * (BN / WN);
    constexpr int NT = NWARP * 32;
    constexpr int MFRAG = WM / 16;
    constexpr int NFRAG = WN / 8;
    static_assert(BM * (BK / 16) == NT, "A staging map");

    __shared__ __half As[BM * LDA];
    __shared__ __half Bh[BN * LDB];
    __shared__ __half Bl[BN * LDB];

    const int tid  = threadIdx.x;
    const int lane = tid & 31;
    const int warp = tid >> 5;
    const int wm0 = (warp / (BN / WN)) * WM;
    const int wn0 = (warp % (BN / WN)) * WN;
    const int bm0 = blockIdx.x * BM;
    const int bn0 = blockIdx.y * BN;

    float mu = 0.f, inv = 1.f;
    if (LNA) { mu = g_ln[0]; inv = g_ln[1]; }

    float acc[MFRAG][NFRAG][4];
#pragma unroll
    for (int i = 0; i < MFRAG; i++)
#pragma unroll
        for (int j = 0; j < NFRAG; j++)
#pragma unroll
            for (int q = 0; q < 4; q++) acc[i][j][q] = 0.f;

    const int gr = lane >> 2;
    const int gc = lane & 3;

    // A staging: 2 threads per row, 16 consecutive k each
    const int am = tid >> 1;
    const int aq = tid & 1;
    const int arow = bm0 + am;

    for (int k0 = 0; k0 < K; k0 += BK) {
        // ---- stage A (fp16 round, optional LN) ----
        {
            __half2 hv[8];
            if (arow < M) {
                if (A_HALF) {
                    const __half* A16 = (const __half*)Ap;
                    float4 r0 = *reinterpret_cast<const float4*>(&A16[(size_t)arow * K + k0 + aq * 16]);
                    float4 r1 = *reinterpret_cast<const float4*>(&A16[(size_t)arow * K + k0 + aq * 16 + 8]);
                    const __half2* p0 = reinterpret_cast<const __half2*>(&r0);
                    const __half2* p1 = reinterpret_cast<const __half2*>(&r1);
                    if (LNA) {
#pragma unroll
                        for (int q = 0; q < 4; q++) {
                            float2 f = __half22float2(p0[q]);
                            hv[q] = __floats2half2_rn((f.x - mu) * inv, (f.y - mu) * inv);
                        }
#pragma unroll
                        for (int q = 0; q < 4; q++) {
                            float2 f = __half22float2(p1[q]);
                            hv[q + 4] = __floats2half2_rn((f.x - mu) * inv, (f.y - mu) * inv);
                        }
                    } else {
#pragma unroll
                        for (int q = 0; q < 4; q++) { hv[q] = p0[q]; hv[q + 4] = p1[q]; }
                    }
                } else {
                    const float* Af = (const float*)Ap;
#pragma unroll
                    for (int q = 0; q < 4; q++) {
                        float4 v = *reinterpret_cast<const float4*>(&Af[(size_t)arow * K + k0 + aq * 16 + q * 4]);
                        if (LNA) {
                            v.x = (v.x - mu) * inv; v.y = (v.y - mu) * inv;
                            v.z = (v.z - mu) * inv; v.w = (v.w - mu) * inv;
                        }
                        hv[q * 2]     = __floats2half2_rn(v.x, v.y);
                        hv[q * 2 + 1] = __floats2half2_rn(v.z, v.w);
                    }
                }
            } else {
#pragma unroll
                for (int q = 0; q < 8; q++) hv[q] = __floats2half2_rn(0.f, 0.f);
            }
#pragma unroll
            for (int q = 0; q < 8; q++)
                *reinterpret_cast<__half2*>(&As[am * LDA + aq * 16 + q * 2]) = hv[q];
        }
        // ---- stage B (split hi/lo, transposed [n][k]) ----
#pragma unroll
        for (int p = 0; p < (BK * BN / 4) / NT; p++) {
            int idx = tid + p * NT;
            int bk = idx / (BN / 4), bn4 = idx % (BN / 4);
            float4 v = *reinterpret_cast<const float4*>(&B[(size_t)(k0 + bk) * Nn + bn0 + bn4 * 4]);
            float f[4] = {v.x, v.y, v.z, v.w};
#pragma unroll
            for (int q = 0; q < 4; q++) {
                __half h = __float2half_rn(f[q]);
                __half l = __float2half_rn(f[q] - __half2float(h));
                Bh[(bn4 * 4 + q) * LDB + bk] = h;
                Bl[(bn4 * 4 + q) * LDB + bk] = l;
            }
        }
        __syncthreads();

#pragma unroll
        for (int ks = 0; ks < BK / 16; ks++) {
            const int kb = ks * 16;
            unsigned a[MFRAG][4];
#pragma unroll
            for (int mi = 0; mi < MFRAG; mi++) {
                int r = wm0 + mi * 16 + gr;
                a[mi][0] = *reinterpret_cast<const unsigned*>(&As[r * LDA + kb + 2 * gc]);
                a[mi][1] = *reinterpret_cast<const unsigned*>(&As[(r + 8) * LDA + kb + 2 * gc]);
                a[mi][2] = *reinterpret_cast<const unsigned*>(&As[r * LDA + kb + 2 * gc + 8]);
                a[mi][3] = *reinterpret_cast<const unsigned*>(&As[(r + 8) * LDA + kb + 2 * gc + 8]);
            }
            unsigned bhr[NFRAG][2], blr[NFRAG][2];
#pragma unroll
            for (int ni = 0; ni < NFRAG; ni++) {
                int c = wn0 + ni * 8 + gr;
                bhr[ni][0] = *reinterpret_cast<const unsigned*>(&Bh[c * LDB + kb + 2 * gc]);
                bhr[ni][1] = *reinterpret_cast<const unsigned*>(&Bh[c * LDB + kb + 2 * gc + 8]);
                blr[ni][0] = *reinterpret_cast<const unsigned*>(&Bl[c * LDB + kb + 2 * gc]);
                blr[ni][1] = *reinterpret_cast<const unsigned*>(&Bl[c * LDB + kb + 2 * gc + 8]);
            }
#pragma unroll
            for (int mi = 0; mi < MFRAG; mi++)
#pragma unroll
                for (int ni = 0; ni < NFRAG; ni++) {
#define MMA_F16(B0,B1)                                                           \
    asm volatile("mma.sync.aligned.m16n8k16.row.col.f32.f16.f16.f32 "            \
                 "{%0,%1,%2,%3}, {%4,%5,%6,%7}, {%8,%9}, {%0,%1,%2,%3};"         \
                 : "+f"(acc[mi][ni][0]), "+f"(acc[mi][ni][1]),                   \
                   "+f"(acc[mi][ni][2]), "+f"(acc[mi][ni][3])                    \
                 : "r"(a[mi][0]), "r"(a[mi][1]), "r"(a[mi][2]), "r"(a[mi][3]),   \
                   "r"(B0), "r"(B1))
                    MMA_F16(blr[ni][0], blr[ni][1]);
                    MMA_F16(bhr[ni][0], bhr[ni][1]);
#undef MMA_F16
                }
        }
        __syncthreads();
    }

    // ---- epilogue ----
    double psum = 0.0, psq = 0.0;
#pragma unroll
    for (int mi = 0; mi < MFRAG; mi++) {
#pragma unroll
        for (int ni = 0; ni < NFRAG; ni++) {
            int c0 = bn0 + wn0 + ni * 8 + gc * 2;
            float2 bb = make_float2(0.f, 0.f);
            if (BIAS_RELU) bb = *reinterpret_cast<const float2*>(&bias[c0]);
#pragma unroll
            for (int half = 0; half < 2; half++) {
                int row = bm0 + wm0 + mi * 16 + gr + half * 8;
                if (row >= M) continue;
                float x = acc[mi][ni][half * 2 + 0];
                float y = acc[mi][ni][half * 2 + 1];
                if (BIAS_RELU) {
                    x = fmaxf(x + bb.x, 0.f);
                    y = fmaxf(y + bb.y, 0.f);
                }
                if (C_HALF) {
                    __half* C16 = (__half*)Cp;
                    *reinterpret_cast<__half2*>(&C16[(size_t)row * Nn + c0]) =
                        __floats2half2_rn(x, y);
                } else {
                    float* Cf = (float*)Cp;
                    *reinterpret_cast<float2*>(&Cf[(size_t)row * Nn + c0]) = make_float2(x, y);
                }
                if (STATS) {
                    psum += (double)x + (double)y;
                    psq  += (double)x * x + (double)y * y;
                }
            }
        }
    }

    if (STATS) {
#pragma unroll
        for (int off = 16; off > 0; off >>= 1) {
            psum += __shfl_down_sync(0xffffffffu, psum, off);
            psq  += __shfl_down_sync(0xffffffffu, psq, off);
        }
        if (lane == 0) {
            atomicAdd(&g_stats[0], psum);
            atomicAdd(&g_stats[1], psq);
        }
    }
}

__global__ void k_finalize(double count) {
    double s = g_stats[0], ss = g_stats[1];
    double mu = s / count;
    double var = ss / count - mu * mu;
    g_ln[0] = (float)mu;
    g_ln[1] = (float)(1.0 / sqrt(var + (double)LN_EPS));
    g_stats[0] = 0.0;
    g_stats[1] = 0.0;
}

// ---------------- launch ----------------
extern "C" void kernel_launch(void* const* d_in, const int* in_sizes, int n_in,
                              void* d_out, int out_size) {
    const float* feat = (const float*)d_in[0];
    const int*   src  = (const int*)d_in[1];
    const int*   dst  = (const int*)d_in[2];
    const float* W0   = (const float*)d_in[3];
    const float* b0   = (const float*)d_in[4];
    const float* W1   = (const float*)d_in[5];
    const float* b1   = (const float*)d_in[6];
    const float* W2   = (const float*)d_in[7];
    const float* b2   = (const float*)d_in[8];
    float* out = (float*)d_out;

    __half *x16 = nullptr, *h16 = nullptr;
    float *agg = nullptr, *tbuf = nullptr;
    cudaGetSymbolAddress((void**)&x16, g_x16);
    cudaGetSymbolAddress((void**)&h16, g_h16);
    cudaGetSymbolAddress((void**)&agg, g_agg);
    cudaGetSymbolAddress((void**)&tbuf, g_t);

    const int NB_N = (NN_NODES + 255) / 256;
    const int NB_E = (EE_EDGES + 255) / 256;
    const int NB_W = (NN_NODES * 32 + 255) / 256;  // warp per row
    const int NB_C = ((NN_NODES * FDIM / 8) + 255) / 256;

    // setup: degrees, norms, CSR (by dst), fp16 features
    k_init<<<NB_N, 256>>>();
    k_degrees<<<NB_E, 256>>>(src, dst);
    k_scan<<<1, 1024>>>();
    k_fill<<<NB_E, 256>>>(src, dst);
    k_cvt<<<NB_C, 256>>>(feat, x16, NN_NODES * FDIM / 8);

    const int GM = (NN_NODES + 127) / 128;
    const double cnt = (double)NN_NODES * FDIM;

    // layer 1: agg = DAD*X ; h1 = relu(agg@W0 + b0) (+stats), h1 stored fp16
    k_spmm256<false><<<NB_W, 256>>>(x16, agg);
    k_gemm16<128, 128, 64, 32, true, true, false, false, true>
        <<<dim3(GM, FDIM / 128), 256>>>(agg, W0, b0, h16, NN_NODES, FDIM, FDIM);
    k_finalize<<<1, 1>>>(cnt);

    // layer 2: agg = DAD*LN(h1) ; h2 = relu(agg@W1 + b1) (+stats), fp16
    k_spmm256<true><<<NB_W, 256>>>(h16, agg);
    k_gemm16<128, 128, 64, 32, true, true, false, false, true>
        <<<dim3(GM, FDIM / 128), 256>>>(agg, W1, b1, h16, NN_NODES, FDIM, FDIM);
    k_finalize<<<1, 1>>>(cnt);

    // layer 3 (reordered): t = LN(h2)@W2 (fp32 out) ; out = DAD*t + b2
    k_gemm16<128, 64, 64, 16, false, false, true, true, false>
        <<<dim3(GM, 1), 256>>>(h16, W2, nullptr, tbuf, NN_NODES, CDIM, FDIM);
    k_spmm64<<<NB_W, 256>>>(tbuf, b2, out);
}

// round 5
// speedup vs baseline: 1.7386x; 1.7386x over previous
#include <cuda_runtime.h>
#include <cuda_fp16.h>
#include <math.h>

#define NN_NODES 100000
#define EE_EDGES 3200000
#define FDIM 256
#define CDIM 64
#define LN_EPS 1e-5

// ---------------- scratch (static device globals; no allocation) ----------------
__device__ int    g_deg_s[NN_NODES];
__device__ int    g_deg_d[NN_NODES];
__device__ float  g_norm_s[NN_NODES];
__device__ float  g_norm_d[NN_NODES];
__device__ int    g_row_off[NN_NODES + 1];
__device__ int    g_cursor[NN_NODES];
__device__ int    g_col[EE_EDGES];
__device__ __half g_x16[(size_t)NN_NODES * FDIM];   // fp16 input features
__device__ __half g_h16[(size_t)NN_NODES * FDIM];   // fp16 hidden
__device__ float  g_agg[(size_t)NN_NODES * FDIM];   // fp32 aggregate (GEMM A)
__device__ float  g_t[(size_t)NN_NODES * CDIM];     // fp32 layer-3 GEMM out
__device__ double g_stats[2];   // sum, sumsq
__device__ float  g_ln[2];      // mu, inv_std
// pre-split, pre-transposed weights: [n][K] fp16 hi/lo
__device__ __half g_w0h[FDIM * FDIM], g_w0l[FDIM * FDIM];
__device__ __half g_w1h[FDIM * FDIM], g_w1l[FDIM * FDIM];
__device__ __half g_w2h[CDIM * FDIM], g_w2l[CDIM * FDIM];

// ---------------- setup kernels ----------------
__global__ void k_init() {
    int i = blockIdx.x * blockDim.x + threadIdx.x;
    if (i < NN_NODES) { g_deg_s[i] = 0; g_deg_d[i] = 0; }
    if (i == 0) { g_stats[0] = 0.0; g_stats[1] = 0.0; }
}

__global__ void k_degrees(const int* __restrict__ src, const int* __restrict__ dst) {
    int e = blockIdx.x * blockDim.x + threadIdx.x;
    if (e < EE_EDGES) {
        atomicAdd(&g_deg_s[src[e]], 1);
        atomicAdd(&g_deg_d[dst[e]], 1);
    }
}

__global__ void k_scan() {
    const int T = 1024;
    int t = threadIdx.x;
    const int chunk = (NN_NODES + T - 1) / T;
    int beg = t * chunk;
    int end = min(beg + chunk, NN_NODES);
    int local = 0;
    for (int i = beg; i < end; i++) local += g_deg_d[i];

    __shared__ int sh[T];
    sh[t] = local;
    __syncthreads();
    for (int off = 1; off < T; off <<= 1) {
        int v = (t >= off) ? sh[t - off] : 0;
        __syncthreads();
        sh[t] += v;
        __syncthreads();
    }
    int run = sh[t] - local;
    for (int i = beg; i < end; i++) {
        g_row_off[i] = run;
        g_cursor[i] = run;
        run += g_deg_d[i];
    }
    if (t == T - 1) g_row_off[NN_NODES] = sh[T - 1];

    for (int i = beg; i < end; i++) {
        g_norm_s[i] = rsqrtf((float)max(g_deg_s[i], 1));
        g_norm_d[i] = rsqrtf((float)max(g_deg_d[i], 1));
    }
}

__global__ void k_fill(const int* __restrict__ src, const int* __restrict__ dst) {
    int e = blockIdx.x * blockDim.x + threadIdx.x;
    if (e < EE_EDGES) {
        int p = atomicAdd(&g_cursor[dst[e]], 1);
        g_col[p] = src[e];
    }
}

// fp32 -> fp16 convert (8 elements/thread)
__global__ void k_cvt(const float* __restrict__ x, __half* __restrict__ y, int n8) {
    int i = blockIdx.x * blockDim.x + threadIdx.x;
    if (i >= n8) return;
    float4 a = reinterpret_cast<const float4*>(x)[i * 2];
    float4 b = reinterpret_cast<const float4*>(x)[i * 2 + 1];
    __half2 h[4];
    h[0] = __floats2half2_rn(a.x, a.y);
    h[1] = __floats2half2_rn(a.z, a.w);
    h[2] = __floats2half2_rn(b.x, b.y);
    h[3] = __floats2half2_rn(b.z, b.w);
    reinterpret_cast<float4*>(y)[i] = *reinterpret_cast<float4*>(h);
}

// pre-split + transpose weights: W[K][N] fp32 -> Wh/Wl[N][K] fp16
__global__ void k_prep_w(const float* __restrict__ W, __half* __restrict__ Wh,
                         __half* __restrict__ Wl, int K, int N) {
    int idx = blockIdx.x * blockDim.x + threadIdx.x;
    if (idx >= K * N) return;
    int k = idx / N, n = idx % N;
    float x = W[idx];
    __half h = __float2half_rn(x);
    __half l = __float2half_rn(x - __half2float(h));
    Wh[n * K + k] = h;
    Wl[n * K + k] = l;
}

// ---------------- SpMM: pull (warp per dst row), fp16 features, fp32 accum ----------------
template <bool LN>
__global__ void k_spmm256(const __half* __restrict__ hin, float* __restrict__ out) {
    int gw = (blockIdx.x * blockDim.x + threadIdx.x) >> 5;
    int lane = threadIdx.x & 31;
    if (gw >= NN_NODES) return;

    float mu = 0.f, inv = 1.f;
    if (LN) { mu = g_ln[0]; inv = g_ln[1]; }

    int s0 = g_row_off[gw], s1 = g_row_off[gw + 1];
    float acc[8];
#pragma unroll
    for (int t = 0; t < 8; t++) acc[t] = 0.f;

    const float4* __restrict__ h4 = reinterpret_cast<const float4*>(hin); // 8 halves each

    for (int base = s0; base < s1; base += 32) {
        int kk = base + lane;
        int j = 0; float sc = 0.f;
        if (kk < s1) { j = g_col[kk]; sc = g_norm_s[j]; }
        int cnt = min(32, s1 - base);
#pragma unroll 8
        for (int i = 0; i < cnt; i++) {
            int   jj = __shfl_sync(0xffffffffu, j, i);
            float sj = __shfl_sync(0xffffffffu, sc, i);
            float4 raw = h4[(size_t)jj * 32 + lane];    // 8 halves
            const __half2* hp = reinterpret_cast<const __half2*>(&raw);
            float2 f0 = __half22float2(hp[0]);
            float2 f1 = __half22float2(hp[1]);
            float2 f2 = __half22float2(hp[2]);
            float2 f3 = __half22float2(hp[3]);
            float sv = LN ? (sj * inv) : sj;
            if (LN) {
                acc[0] = fmaf(f0.x - mu, sv, acc[0]); acc[1] = fmaf(f0.y - mu, sv, acc[1]);
                acc[2] = fmaf(f1.x - mu, sv, acc[2]); acc[3] = fmaf(f1.y - mu, sv, acc[3]);
                acc[4] = fmaf(f2.x - mu, sv, acc[4]); acc[5] = fmaf(f2.y - mu, sv, acc[5]);
                acc[6] = fmaf(f3.x - mu, sv, acc[6]); acc[7] = fmaf(f3.y - mu, sv, acc[7]);
            } else {
                acc[0] = fmaf(f0.x, sv, acc[0]); acc[1] = fmaf(f0.y, sv, acc[1]);
                acc[2] = fmaf(f1.x, sv, acc[2]); acc[3] = fmaf(f1.y, sv, acc[3]);
                acc[4] = fmaf(f2.x, sv, acc[4]); acc[5] = fmaf(f2.y, sv, acc[5]);
                acc[6] = fmaf(f3.x, sv, acc[6]); acc[7] = fmaf(f3.y, sv, acc[7]);
            }
        }
    }
    float nd = g_norm_d[gw];
    float4 o0 = make_float4(acc[0] * nd, acc[1] * nd, acc[2] * nd, acc[3] * nd);
    float4 o1 = make_float4(acc[4] * nd, acc[5] * nd, acc[6] * nd, acc[7] * nd);
    float4* o4 = reinterpret_cast<float4*>(out);
    o4[(size_t)gw * 64 + lane * 2]     = o0;
    o4[(size_t)gw * 64 + lane * 2 + 1] = o1;
}

// ---------------- SpMM 64-wide (final layer, with bias) ----------------
__global__ void k_spmm64(const float* __restrict__ tin, const float* __restrict__ bias,
                         float* __restrict__ out) {
    int gw = (blockIdx.x * blockDim.x + threadIdx.x) >> 5;
    int lane = threadIdx.x & 31;
    if (gw >= NN_NODES) return;

    int s0 = g_row_off[gw], s1 = g_row_off[gw + 1];
    float2 a = make_float2(0.f, 0.f);
    const float2* __restrict__ t2 = reinterpret_cast<const float2*>(tin);

    for (int base = s0; base < s1; base += 32) {
        int kk = base + lane;
        int j = 0; float sc = 0.f;
        if (kk < s1) { j = g_col[kk]; sc = g_norm_s[j]; }
        int cnt = min(32, s1 - base);
#pragma unroll 8
        for (int i = 0; i < cnt; i++) {
            int   jj = __shfl_sync(0xffffffffu, j, i);
            float sj = __shfl_sync(0xffffffffu, sc, i);
            float2 v = t2[(size_t)jj * (CDIM / 2) + lane];
            a.x = fmaf(v.x, sj, a.x);
            a.y = fmaf(v.y, sj, a.y);
        }
    }
    float nd = g_norm_d[gw];
    float2 b = reinterpret_cast<const float2*>(bias)[lane];
    float2 o;
    o.x = fmaf(a.x, nd, b.x);
    o.y = fmaf(a.y, nd, b.y);
    reinterpret_cast<float2*>(out)[(size_t)gw * (CDIM / 2) + lane] = o;
}

// ---------------- fp16 tensor-core GEMM, A split hi+lo, B pre-split hi+lo ----------------
// C = op(A) @ W, 3 MMAs per frag pair: Ah*Bh + Ah*Bl + Al*Bh (error ~2^-22)
template <int BM, int BN, int WM, int WN, bool BIAS_RELU, bool STATS, bool LNA,
          bool A_HALF, bool C_HALF>
__global__ void k_gemm16(const void* __restrict__ Ap,
                         const __half* __restrict__ Bh_g,   // [n][K] fp16 hi
                         const __half* __restrict__ Bl_g,   // [n][K] fp16 lo
                         const float* __restrict__ bias, void* __restrict__ Cp,
                         int M, int Nn, int K) {
    constexpr int BK = 32;
    constexpr int LDA = BK + 8;          // halves; pitch 80B -> conflict-free frags
    constexpr int LDB = BK + 8;
    constexpr int NWARP = (BM / WM) * (BN / WN);
    constexpr int NT = NWARP * 32;
    constexpr int MFRAG = WM / 16;
    constexpr int NFRAG = WN / 8;
    static_assert(BM * (BK / 16) == NT, "A staging map");

    __shared__ __half As_h[BM * LDA];
    __shared__ __half As_l[BM * LDA];
    __shared__ __half Bs_h[BN * LDB];
    __shared__ __half Bs_l[BN * LDB];

    const int tid  = threadIdx.x;
    const int lane = tid & 31;
    const int warp = tid >> 5;
    const int wm0 = (warp / (BN / WN)) * WM;
    const int wn0 = (warp % (BN / WN)) * WN;
    const int bm0 = blockIdx.x * BM;
    const int bn0 = blockIdx.y * BN;

    float mu = 0.f, inv = 1.f;
    if (LNA) { mu = g_ln[0]; inv = g_ln[1]; }

    float acc[MFRAG][NFRAG][4];
#pragma unroll
    for (int i = 0; i < MFRAG; i++)
#pragma unroll
        for (int j = 0; j < NFRAG; j++)
#pragma unroll
            for (int q = 0; q < 4; q++) acc[i][j][q] = 0.f;

    const int gr = lane >> 2;
    const int gc = lane & 3;

    // A staging: 2 threads per row, 16 consecutive k each
    const int am = tid >> 1;
    const int aq = tid & 1;
    const int arow = bm0 + am;

    for (int k0 = 0; k0 < K; k0 += BK) {
        // ---- stage A (split hi/lo, optional LN), float4 writes ----
        {
            float v[16];
            if (arow < M) {
                if (A_HALF) {
                    const __half* A16 = (const __half*)Ap;
                    float4 r0 = *reinterpret_cast<const float4*>(&A16[(size_t)arow * K + k0 + aq * 16]);
                    float4 r1 = *reinterpret_cast<const float4*>(&A16[(size_t)arow * K + k0 + aq * 16 + 8]);
                    const __half2* p0 = reinterpret_cast<const __half2*>(&r0);
                    const __half2* p1 = reinterpret_cast<const __half2*>(&r1);
#pragma unroll
                    for (int q = 0; q < 4; q++) {
                        float2 f = __half22float2(p0[q]);
                        v[q * 2] = f.x; v[q * 2 + 1] = f.y;
                    }
#pragma unroll
                    for (int q = 0; q < 4; q++) {
                        float2 f = __half22float2(p1[q]);
                        v[8 + q * 2] = f.x; v[8 + q * 2 + 1] = f.y;
                    }
                } else {
                    const float* Af = (const float*)Ap;
#pragma unroll
                    for (int q = 0; q < 4; q++) {
                        float4 r = *reinterpret_cast<const float4*>(&Af[(size_t)arow * K + k0 + aq * 16 + q * 4]);
                        v[q * 4] = r.x; v[q * 4 + 1] = r.y; v[q * 4 + 2] = r.z; v[q * 4 + 3] = r.w;
                    }
                }
            } else {
#pragma unroll
                for (int q = 0; q < 16; q++) v[q] = 0.f;
            }
            __half2 hh[8], hl[8];
#pragma unroll
            for (int q = 0; q < 8; q++) {
                float x0 = v[q * 2], x1 = v[q * 2 + 1];
                if (LNA) { x0 = (x0 - mu) * inv; x1 = (x1 - mu) * inv; }
                __half h0 = __float2half_rn(x0);
                __half h1 = __float2half_rn(x1);
                hh[q] = __halves2half2(h0, h1);
                hl[q] = __floats2half2_rn(x0 - __half2float(h0), x1 - __half2float(h1));
            }
            float4* ph = reinterpret_cast<float4*>(&As_h[am * LDA + aq * 16]);
            float4* pl = reinterpret_cast<float4*>(&As_l[am * LDA + aq * 16]);
            ph[0] = reinterpret_cast<float4*>(hh)[0];
            ph[1] = reinterpret_cast<float4*>(hh)[1];
            pl[0] = reinterpret_cast<float4*>(hl)[0];
            pl[1] = reinterpret_cast<float4*>(hl)[1];
        }
        // ---- stage B: straight float4 copies from pre-split [n][K] fp16 ----
        constexpr int B4 = BN * BK / 8;   // float4 count
#pragma unroll
        for (int p = 0; p < B4 / NT; p++) {
            int idx = tid + p * NT;
            int n = idx / (BK / 8), seg = idx % (BK / 8);
            size_t goff = (size_t)(bn0 + n) * K + k0 + seg * 8;
            *reinterpret_cast<float4*>(&Bs_h[n * LDB + seg * 8]) =
                *reinterpret_cast<const float4*>(&Bh_g[goff]);
            *reinterpret_cast<float4*>(&Bs_l[n * LDB + seg * 8]) =
                *reinterpret_cast<const float4*>(&Bl_g[goff]);
        }
        __syncthreads();

#pragma unroll
        for (int ks = 0; ks < BK / 16; ks++) {
            const int kb = ks * 16;
            unsigned ah[MFRAG][4], al[MFRAG][4];
#pragma unroll
            for (int mi = 0; mi < MFRAG; mi++) {
                int r = wm0 + mi * 16 + gr;
                ah[mi][0] = *reinterpret_cast<const unsigned*>(&As_h[r * LDA + kb + 2 * gc]);
                ah[mi][1] = *reinterpret_cast<const unsigned*>(&As_h[(r + 8) * LDA + kb + 2 * gc]);
                ah[mi][2] = *reinterpret_cast<const unsigned*>(&As_h[r * LDA + kb + 2 * gc + 8]);
                ah[mi][3] = *reinterpret_cast<const unsigned*>(&As_h[(r + 8) * LDA + kb + 2 * gc + 8]);
                al[mi][0] = *reinterpret_cast<const unsigned*>(&As_l[r * LDA + kb + 2 * gc]);
                al[mi][1] = *reinterpret_cast<const unsigned*>(&As_l[(r + 8) * LDA + kb + 2 * gc]);
                al[mi][2] = *reinterpret_cast<const unsigned*>(&As_l[r * LDA + kb + 2 * gc + 8]);
                al[mi][3] = *reinterpret_cast<const unsigned*>(&As_l[(r + 8) * LDA + kb + 2 * gc + 8]);
            }
            unsigned bh[NFRAG][2], bl[NFRAG][2];
#pragma unroll
            for (int ni = 0; ni < NFRAG; ni++) {
                int c = wn0 + ni * 8 + gr;
                bh[ni][0] = *reinterpret_cast<const unsigned*>(&Bs_h[c * LDB + kb + 2 * gc]);
                bh[ni][1] = *reinterpret_cast<const unsigned*>(&Bs_h[c * LDB + kb + 2 * gc + 8]);
                bl[ni][0] = *reinterpret_cast<const unsigned*>(&Bs_l[c * LDB + kb + 2 * gc]);
                bl[ni][1] = *reinterpret_cast<const unsigned*>(&Bs_l[c * LDB + kb + 2 * gc + 8]);
            }
#pragma unroll
            for (int mi = 0; mi < MFRAG; mi++)
#pragma unroll
                for (int ni = 0; ni < NFRAG; ni++) {
#define MMA_F16(A0,A1,A2,A3,B0,B1)                                               \
    asm volatile("mma.sync.aligned.m16n8k16.row.col.f32.f16.f16.f32 "            \
                 "{%0,%1,%2,%3}, {%4,%5,%6,%7}, {%8,%9}, {%0,%1,%2,%3};"         \
                 : "+f"(acc[mi][ni][0]), "+f"(acc[mi][ni][1]),                   \
                   "+f"(acc[mi][ni][2]), "+f"(acc[mi][ni][3])                    \
                 : "r"(A0), "r"(A1), "r"(A2), "r"(A3), "r"(B0), "r"(B1))
                    MMA_F16(ah[mi][0], ah[mi][1], ah[mi][2], ah[mi][3], bl[ni][0], bl[ni][1]);
                    MMA_F16(al[mi][0], al[mi][1], al[mi][2], al[mi][3], bh[ni][0], bh[ni][1]);
                    MMA_F16(ah[mi][0], ah[mi][1], ah[mi][2], ah[mi][3], bh[ni][0], bh[ni][1]);
#undef MMA_F16
                }
        }
        __syncthreads();
    }

    // ---- epilogue ----
    double psum = 0.0, psq = 0.0;
#pragma unroll
    for (int mi = 0; mi < MFRAG; mi++) {
#pragma unroll
        for (int ni = 0; ni < NFRAG; ni++) {
            int c0 = bn0 + wn0 + ni * 8 + gc * 2;
            float2 bb = make_float2(0.f, 0.f);
            if (BIAS_RELU) bb = *reinterpret_cast<const float2*>(&bias[c0]);
#pragma unroll
            for (int half = 0; half < 2; half++) {
                int row = bm0 + wm0 + mi * 16 + gr + half * 8;
                if (row >= M) continue;
                float x = acc[mi][ni][half * 2 + 0];
                float y = acc[mi][ni][half * 2 + 1];
                if (BIAS_RELU) {
                    x = fmaxf(x + bb.x, 0.f);
                    y = fmaxf(y + bb.y, 0.f);
                }
                if (C_HALF) {
                    __half* C16 = (__half*)Cp;
                    *reinterpret_cast<__half2*>(&C16[(size_t)row * Nn + c0]) =
                        __floats2half2_rn(x, y);
                } else {
                    float* Cf = (float*)Cp;
                    *reinterpret_cast<float2*>(&Cf[(size_t)row * Nn + c0]) = make_float2(x, y);
                }
                if (STATS) {
                    psum += (double)x + (double)y;
                    psq  += (double)x * x + (double)y * y;
                }
            }
        }
    }

    if (STATS) {
#pragma unroll
        for (int off = 16; off > 0; off >>= 1) {
            psum += __shfl_down_sync(0xffffffffu, psum, off);
            psq  += __shfl_down_sync(0xffffffffu, psq, off);
        }
        if (lane == 0) {
            atomicAdd(&g_stats[0], psum);
            atomicAdd(&g_stats[1], psq);
        }
    }
}

__global__ void k_finalize(double count) {
    double s = g_stats[0], ss = g_stats[1];
    double mu = s / count;
    double var = ss / count - mu * mu;
    g_ln[0] = (float)mu;
    g_ln[1] = (float)(1.0 / sqrt(var + (double)LN_EPS));
    g_stats[0] = 0.0;
    g_stats[1] = 0.0;
}

// ---------------- launch ----------------
extern "C" void kernel_launch(void* const* d_in, const int* in_sizes, int n_in,
                              void* d_out, int out_size) {
    const float* feat = (const float*)d_in[0];
    const int*   src  = (const int*)d_in[1];
    const int*   dst  = (const int*)d_in[2];
    const float* W0   = (const float*)d_in[3];
    const float* b0   = (const float*)d_in[4];
    const float* W1   = (const float*)d_in[5];
    const float* b1   = (const float*)d_in[6];
    const float* W2   = (const float*)d_in[7];
    const float* b2   = (const float*)d_in[8];
    float* out = (float*)d_out;

    __half *x16 = nullptr, *h16 = nullptr;
    float *agg = nullptr, *tbuf = nullptr;
    __half *w0h, *w0l, *w1h, *w1l, *w2h, *w2l;
    cudaGetSymbolAddress((void**)&x16, g_x16);
    cudaGetSymbolAddress((void**)&h16, g_h16);
    cudaGetSymbolAddress((void**)&agg, g_agg);
    cudaGetSymbolAddress((void**)&tbuf, g_t);
    cudaGetSymbolAddress((void**)&w0h, g_w0h);
    cudaGetSymbolAddress((void**)&w0l, g_w0l);
    cudaGetSymbolAddress((void**)&w1h, g_w1h);
    cudaGetSymbolAddress((void**)&w1l, g_w1l);
    cudaGetSymbolAddress((void**)&w2h, g_w2h);
    cudaGetSymbolAddress((void**)&w2l, g_w2l);

    const int NB_N = (NN_NODES + 255) / 256;
    const int NB_E = (EE_EDGES + 255) / 256;
    const int NB_W = (NN_NODES * 32 + 255) / 256;  // warp per row
    const int NB_C = ((NN_NODES * FDIM / 8) + 255) / 256;

    // setup: degrees, norms, CSR (by dst), fp16 features, split weights
    k_init<<<NB_N, 256>>>();
    k_degrees<<<NB_E, 256>>>(src, dst);
    k_scan<<<1, 1024>>>();
    k_fill<<<NB_E, 256>>>(src, dst);
    k_cvt<<<NB_C, 256>>>(feat, x16, NN_NODES * FDIM / 8);
    k_prep_w<<<(FDIM * FDIM + 255) / 256, 256>>>(W0, w0h, w0l, FDIM, FDIM);
    k_prep_w<<<(FDIM * FDIM + 255) / 256, 256>>>(W1, w1h, w1l, FDIM, FDIM);
    k_prep_w<<<(FDIM * CDIM + 255) / 256, 256>>>(W2, w2h, w2l, FDIM, CDIM);

    const int GM = (NN_NODES + 127) / 128;
    const double cnt = (double)NN_NODES * FDIM;

    // layer 1: agg = DAD*X ; h1 = relu(agg@W0 + b0) (+stats), h1 stored fp16
    k_spmm256<false><<<NB_W, 256>>>(x16, agg);
    k_gemm16<128, 128, 64, 32, true, true, false, false, true>
        <<<dim3(GM, FDIM / 128), 256>>>(agg, w0h, w0l, b0, h16, NN_NODES, FDIM, FDIM);
    k_finalize<<<1, 1>>>(cnt);

    // layer 2: agg = DAD*LN(h1) ; h2 = relu(agg@W1 + b1) (+stats), fp16
    k_spmm256<true><<<NB_W, 256>>>(h16, agg);
    k_gemm16<128, 128, 64, 32, true, true, false, false, true>
        <<<dim3(GM, FDIM / 128), 256>>>(agg, w1h, w1l, b1, h16, NN_NODES, FDIM, FDIM);
    k_finalize<<<1, 1>>>(cnt);

    // layer 3 (reordered): t = LN(h2)@W2 (fp32 out) ; out = DAD*t + b2
    k_gemm16<128, 64, 64, 16, false, false, true, true, false>
        <<<dim3(GM, 1), 256>>>(h16, w2h, w2l, nullptr, tbuf, NN_NODES, CDIM, FDIM);
    k_spmm64<<<NB_W, 256>>>(tbuf, b2, out);
}